// round 5
// baseline (speedup 1.0000x reference)
#include <cuda_runtime.h>
#include <cuda_fp16.h>

#define BATCH     32
#define CHANNELS  3
#define HIMG      512
#define WIMG      512
#define PLANE     (HIMG * WIMG)            // pixels per image plane
#define PXTOT     (BATCH * PLANE)          // 8388608 pixels
#define THREADS   256
#define NBLOCKS   (BATCH * HIMG)
#define INV_NELEM (1.0f / (float)(BATCH * CHANNELS * HIMG * WIMG))

// 64MB interleaved fp16x4 image: [B, H, W, 4] (c0,c1,c2,pad). Static scratch.
__device__ __half2      g_img[PXTOT * 2];
// self-resetting cross-block reduction state
__device__ float        g_acc;
__device__ unsigned int g_ticket;

// ---------------------------------------------------------------------------
// Prepass: planar fp32 [B,3,H,W] -> interleaved fp16x4 [B,H,W,4]
// one thread = 4 consecutive pixels (float4 per channel, 2x uint4 out)
// ---------------------------------------------------------------------------
__global__ void __launch_bounds__(THREADS)
interleave_kernel(const float* __restrict__ I) {
    int t   = blockIdx.x * blockDim.x + threadIdx.x;   // < PXTOT/4 exactly
    int px  = t << 2;
    int b   = px >> 18;                                // PLANE = 2^18
    int off = px & (PLANE - 1);
    const float* base = I + (size_t)b * (CHANNELS * PLANE) + off;
    float4 c0 = *(const float4*)(base);
    float4 c1 = *(const float4*)(base + PLANE);
    float4 c2 = *(const float4*)(base + 2 * PLANE);

    __half2 o[8];
    o[0] = __floats2half2_rn(c0.x, c1.x);
    o[1] = __floats2half2_rn(c2.x, 0.0f);
    o[2] = __floats2half2_rn(c0.y, c1.y);
    o[3] = __floats2half2_rn(c2.y, 0.0f);
    o[4] = __floats2half2_rn(c0.z, c1.z);
    o[5] = __floats2half2_rn(c2.z, 0.0f);
    o[6] = __floats2half2_rn(c0.w, c1.w);
    o[7] = __floats2half2_rn(c2.w, 0.0f);

    uint4* dst = reinterpret_cast<uint4*>(g_img + (size_t)px * 2);  // 32B aligned
    dst[0] = *reinterpret_cast<uint4*>(&o[0]);
    dst[1] = *reinterpret_cast<uint4*>(&o[4]);
}

// ---------------------------------------------------------------------------
// 3x3 inverse via adjugate
// ---------------------------------------------------------------------------
__device__ __forceinline__ void invert3x3(const float* __restrict__ m,
                                          float* __restrict__ inv) {
    float c00 = m[4] * m[8] - m[5] * m[7];
    float c01 = m[5] * m[6] - m[3] * m[8];
    float c02 = m[3] * m[7] - m[4] * m[6];
    float det = m[0] * c00 + m[1] * c01 + m[2] * c02;
    float id  = 1.0f / det;
    inv[0] = c00 * id;
    inv[1] = (m[2] * m[7] - m[1] * m[8]) * id;
    inv[2] = (m[1] * m[5] - m[2] * m[4]) * id;
    inv[3] = c01 * id;
    inv[4] = (m[0] * m[8] - m[2] * m[6]) * id;
    inv[5] = (m[2] * m[3] - m[0] * m[5]) * id;
    inv[6] = c02 * id;
    inv[7] = (m[1] * m[6] - m[0] * m[7]) * id;
    inv[8] = (m[0] * m[4] - m[1] * m[3]) * id;
}

// ---------------------------------------------------------------------------
// Lean bilinear taps (pixel-unit offsets into the interleaved image)
// ---------------------------------------------------------------------------
struct Taps {
    int   o00;                  // +1, +512, +513 for the other taps
    float w00, w10, w01, w11;
};

__device__ __forceinline__ Taps make_taps(float sx, float sy) {
    float x0f = floorf(sx), y0f = floorf(sy);
    float wx1 = sx - x0f, wx0 = 1.0f - wx1;
    float wy1 = sy - y0f, wy0 = 1.0f - wy1;
    int x0 = (int)x0f, y0 = (int)y0f;
    bool vx0 = (unsigned)x0       < WIMG;
    bool vx1 = (unsigned)(x0 + 1) < WIMG;
    bool vy0 = (unsigned)y0       < HIMG;
    bool vy1 = (unsigned)(y0 + 1) < HIMG;
    float wx0m = vx0 ? wx0 : 0.0f;
    float wx1m = vx1 ? wx1 : 0.0f;
    float wy0m = vy0 ? wy0 : 0.0f;
    float wy1m = vy1 ? wy1 : 0.0f;
    Taps tp;
    tp.o00 = y0 * WIMG + x0;
    tp.w00 = wx0m * wy0m;
    tp.w10 = wx1m * wy0m;
    tp.w01 = wx0m * wy1m;
    tp.w11 = wx1m * wy1m;
    return tp;
}

#define CW (512.0f / 511.0f)
#define CH (512.0f / 511.0f)

__device__ __forceinline__ Taps proj_taps(float X, float Y, float Z) {
    float iz = __fdividef(1.0f, Z);
    float sx = fmaf(X * iz, CW, -0.5f);
    float sy = fmaf(Y * iz, CH, -0.5f);
    return make_taps(sx, sy);
}

// one tap: predicated LDG.64 fetches all 3 channels; dead taps add 0
__device__ __forceinline__ void tap_acc(const uint2* __restrict__ img, int o, float w,
                                        float& a0, float& a1, float& a2) {
    uint2 v = (w != 0.0f) ? __ldg(img + o) : make_uint2(0u, 0u);
    float2 c01 = __half22float2(*reinterpret_cast<__half2*>(&v.x));
    float  c2  = __low2float(*reinterpret_cast<__half2*>(&v.y));
    a0 = fmaf(c01.x, w, a0);
    a1 = fmaf(c01.y, w, a1);
    a2 = fmaf(c2,    w, a2);
}

__device__ __forceinline__ void sample3(const uint2* __restrict__ img, const Taps& t,
                                        float& a0, float& a1, float& a2) {
    a0 = a1 = a2 = 0.0f;
    tap_acc(img, t.o00,            t.w00, a0, a1, a2);
    tap_acc(img, t.o00 + 1,        t.w10, a0, a1, a2);
    tap_acc(img, t.o00 + WIMG,     t.w01, a0, a1, a2);
    tap_acc(img, t.o00 + WIMG + 1, t.w11, a0, a1, a2);
}

// ---------------------------------------------------------------------------
// Main kernel: block = (batch,row); thread t handles x = t and x = t+256
// ---------------------------------------------------------------------------
__global__ void __launch_bounds__(THREADS, 6)
pl_kernel(const float* __restrict__ Hp, const float* __restrict__ Ht,
          float* __restrict__ out) {
    __shared__ float shp[9];
    __shared__ float sht[9];
    __shared__ float s_part[THREADS / 32];

    int tid = threadIdx.x;
    int b = blockIdx.x >> 9;
    int y = blockIdx.x & (HIMG - 1);

    if (tid == 0) invert3x3(Hp + b * 9, shp);
    if (tid == 1) invert3x3(Ht + b * 9, sht);
    __syncthreads();

    float fx = (float)tid, fy = (float)y;

    float Xp = fmaf(shp[0], fx, fmaf(shp[1], fy, shp[2]));
    float Yp = fmaf(shp[3], fx, fmaf(shp[4], fy, shp[5]));
    float Zp = fmaf(shp[6], fx, fmaf(shp[7], fy, shp[8]));
    float Xt = fmaf(sht[0], fx, fmaf(sht[1], fy, sht[2]));
    float Yt = fmaf(sht[3], fx, fmaf(sht[4], fy, sht[5]));
    float Zt = fmaf(sht[6], fx, fmaf(sht[7], fy, sht[8]));

    Taps tpP0 = proj_taps(Xp, Yp, Zp);
    Taps tpT0 = proj_taps(Xt, Yt, Zt);
    Taps tpP1 = proj_taps(fmaf(shp[0], 256.0f, Xp),
                          fmaf(shp[3], 256.0f, Yp),
                          fmaf(shp[6], 256.0f, Zp));
    Taps tpT1 = proj_taps(fmaf(sht[0], 256.0f, Xt),
                          fmaf(sht[3], 256.0f, Yt),
                          fmaf(sht[6], 256.0f, Zt));

    const uint2* img = reinterpret_cast<const uint2*>(g_img) + (size_t)b * PLANE;

    float acc = 0.0f;
    {
        float p0, p1, p2, t0, t1, t2;
        sample3(img, tpP0, p0, p1, p2);
        sample3(img, tpT0, t0, t1, t2);
        float d0 = p0 - t0, d1 = p1 - t1, d2 = p2 - t2;
        acc = fmaf(d0, d0, acc);
        acc = fmaf(d1, d1, acc);
        acc = fmaf(d2, d2, acc);
    }
    {
        float p0, p1, p2, t0, t1, t2;
        sample3(img, tpP1, p0, p1, p2);
        sample3(img, tpT1, t0, t1, t2);
        float d0 = p0 - t0, d1 = p1 - t1, d2 = p2 - t2;
        acc = fmaf(d0, d0, acc);
        acc = fmaf(d1, d1, acc);
        acc = fmaf(d2, d2, acc);
    }

    // warp shuffle -> smem -> block partial -> self-resetting global reduce
#pragma unroll
    for (int off = 16; off > 0; off >>= 1)
        acc += __shfl_down_sync(0xFFFFFFFFu, acc, off);

    int lane = tid & 31, wid = tid >> 5;
    if (lane == 0) s_part[wid] = acc;
    __syncthreads();
    if (tid == 0) {
        float v = 0.0f;
#pragma unroll
        for (int i = 0; i < THREADS / 32; i++) v += s_part[i];
        atomicAdd(&g_acc, v * INV_NELEM);
        __threadfence();
        unsigned t = atomicInc(&g_ticket, NBLOCKS - 1);  // wraps -> self-reset
        if (t == NBLOCKS - 1) {
            float r = atomicExch(&g_acc, 0.0f);
            out[0] = r;
        }
    }
}

extern "C" void kernel_launch(void* const* d_in, const int* in_sizes, int n_in,
                              void* d_out, int out_size) {
    const float* Hp = (const float*)d_in[0];
    const float* Ht = (const float*)d_in[1];
    const float* I  = (const float*)d_in[2];
    float* out = (float*)d_out;

    interleave_kernel<<<PXTOT / 4 / THREADS, THREADS>>>(I);
    pl_kernel<<<NBLOCKS, THREADS>>>(Hp, Ht, out);
}

// round 6
// speedup vs baseline: 1.1694x; 1.1694x over previous
#include <cuda_runtime.h>
#include <cuda_fp16.h>

#define BATCH     32
#define CHANNELS  3
#define HIMG      512
#define WIMG      512
#define PLANE     (HIMG * WIMG)
#define PXTOT     (BATCH * PLANE)
#define THREADS   256
#define NBLOCKS   (BATCH * HIMG / 2)       // block = (batch, row-pair): 8192
#define INV_NELEM (1.0f / (float)(BATCH * CHANNELS * HIMG * WIMG))

// 64MB interleaved fp16x4 image: [B, H, W, 4] (c0,c1,c2,pad)
__device__ __half2      g_img[PXTOT * 2];
// self-resetting cross-block reduction state
__device__ float        g_acc;
__device__ unsigned int g_ticket;

// ---------------------------------------------------------------------------
// Prepass: planar fp32 [B,3,H,W] -> interleaved fp16x4 [B,H,W,4]
// ---------------------------------------------------------------------------
__global__ void __launch_bounds__(THREADS)
interleave_kernel(const float* __restrict__ I) {
    int t   = blockIdx.x * blockDim.x + threadIdx.x;   // < PXTOT/4
    int px  = t << 2;
    int b   = px >> 18;
    int off = px & (PLANE - 1);
    const float* base = I + (size_t)b * (CHANNELS * PLANE) + off;
    float4 c0 = *(const float4*)(base);
    float4 c1 = *(const float4*)(base + PLANE);
    float4 c2 = *(const float4*)(base + 2 * PLANE);

    __half2 o[8];
    o[0] = __floats2half2_rn(c0.x, c1.x);
    o[1] = __floats2half2_rn(c2.x, 0.0f);
    o[2] = __floats2half2_rn(c0.y, c1.y);
    o[3] = __floats2half2_rn(c2.y, 0.0f);
    o[4] = __floats2half2_rn(c0.z, c1.z);
    o[5] = __floats2half2_rn(c2.z, 0.0f);
    o[6] = __floats2half2_rn(c0.w, c1.w);
    o[7] = __floats2half2_rn(c2.w, 0.0f);

    uint4* dst = reinterpret_cast<uint4*>(g_img + (size_t)px * 2);
    dst[0] = *reinterpret_cast<uint4*>(&o[0]);
    dst[1] = *reinterpret_cast<uint4*>(&o[4]);
}

// ---------------------------------------------------------------------------
// 3x3 inverse via adjugate
// ---------------------------------------------------------------------------
__device__ __forceinline__ void invert3x3(const float* __restrict__ m,
                                          float* __restrict__ inv) {
    float c00 = m[4] * m[8] - m[5] * m[7];
    float c01 = m[5] * m[6] - m[3] * m[8];
    float c02 = m[3] * m[7] - m[4] * m[6];
    float det = m[0] * c00 + m[1] * c01 + m[2] * c02;
    float id  = 1.0f / det;
    inv[0] = c00 * id;
    inv[1] = (m[2] * m[7] - m[1] * m[8]) * id;
    inv[2] = (m[1] * m[5] - m[2] * m[4]) * id;
    inv[3] = c01 * id;
    inv[4] = (m[0] * m[8] - m[2] * m[6]) * id;
    inv[5] = (m[2] * m[3] - m[0] * m[5]) * id;
    inv[6] = c02 * id;
    inv[7] = (m[1] * m[6] - m[0] * m[7]) * id;
    inv[8] = (m[0] * m[4] - m[1] * m[3]) * id;
}

// ---------------------------------------------------------------------------
// Lean bilinear taps (no clamps; loads predicated on w != 0)
// ---------------------------------------------------------------------------
struct Taps {
    int   o00;
    float w00, w10, w01, w11;
};

__device__ __forceinline__ Taps make_taps(float sx, float sy) {
    float x0f = floorf(sx), y0f = floorf(sy);
    float wx1 = sx - x0f, wx0 = 1.0f - wx1;
    float wy1 = sy - y0f, wy0 = 1.0f - wy1;
    int x0 = (int)x0f, y0 = (int)y0f;
    bool vx0 = (unsigned)x0       < WIMG;
    bool vx1 = (unsigned)(x0 + 1) < WIMG;
    bool vy0 = (unsigned)y0       < HIMG;
    bool vy1 = (unsigned)(y0 + 1) < HIMG;
    float wx0m = vx0 ? wx0 : 0.0f;
    float wx1m = vx1 ? wx1 : 0.0f;
    float wy0m = vy0 ? wy0 : 0.0f;
    float wy1m = vy1 ? wy1 : 0.0f;
    Taps tp;
    tp.o00 = y0 * WIMG + x0;
    tp.w00 = wx0m * wy0m;
    tp.w10 = wx1m * wy0m;
    tp.w01 = wx0m * wy1m;
    tp.w11 = wx1m * wy1m;
    return tp;
}

#define CW (512.0f / 511.0f)
#define CH (512.0f / 511.0f)

__device__ __forceinline__ Taps proj_taps(float X, float Y, float Z) {
    float iz = __fdividef(1.0f, Z);
    float sx = fmaf(X * iz, CW, -0.5f);
    float sy = fmaf(Y * iz, CH, -0.5f);
    return make_taps(sx, sy);
}

// one tap: predicated LDG.64 + 2 HFMA2 (channels 0,1 packed; channel 2 in lo)
__device__ __forceinline__ void tap_acc(const uint2* __restrict__ img, int o, float w,
                                        __half2& a01, __half2& a2) {
    uint2 v = (w != 0.0f) ? __ldg(img + o) : make_uint2(0u, 0u);
    __half2 w2 = __float2half2_rn(w);
    a01 = __hfma2(*reinterpret_cast<__half2*>(&v.x), w2, a01);
    a2  = __hfma2(*reinterpret_cast<__half2*>(&v.y), w2, a2);
}

__device__ __forceinline__ void sample3h(const uint2* __restrict__ img, const Taps& t,
                                         __half2& a01, __half2& a2) {
    a01 = __float2half2_rn(0.0f);
    a2  = __float2half2_rn(0.0f);
    tap_acc(img, t.o00,            t.w00, a01, a2);
    tap_acc(img, t.o00 + 1,        t.w10, a01, a2);
    tap_acc(img, t.o00 + WIMG,     t.w01, a01, a2);
    tap_acc(img, t.o00 + WIMG + 1, t.w11, a01, a2);
}

// full per-pixel MSE contribution (both warps sampled, diff, square)
__device__ __forceinline__ float pixel_mse(const uint2* __restrict__ img,
                                           float Xp, float Yp, float Zp,
                                           float Xt, float Yt, float Zt) {
    Taps tP = proj_taps(Xp, Yp, Zp);
    Taps tT = proj_taps(Xt, Yt, Zt);
    __half2 p01, p2, t01, t2;
    sample3h(img, tP, p01, p2);
    sample3h(img, tT, t01, t2);
    __half2 d01 = __hsub2(p01, t01);
    __half2 d2  = __hsub2(p2, t2);
    float2 f = __half22float2(d01);
    float  g = __low2float(d2);
    return fmaf(f.x, f.x, fmaf(f.y, f.y, g * g));
}

// ---------------------------------------------------------------------------
// Main kernel: block = (batch, row-pair); thread t handles
// (x=t, y0), (x=t+256, y0), (x=t, y0+1), (x=t+256, y0+1)
// ---------------------------------------------------------------------------
__global__ void __launch_bounds__(THREADS)
pl_kernel(const float* __restrict__ Hp, const float* __restrict__ Ht,
          float* __restrict__ out) {
    __shared__ float shp[9];
    __shared__ float sht[9];
    __shared__ float s_part[THREADS / 32];

    int tid = threadIdx.x;
    int b  = blockIdx.x >> 8;               // 256 row-pairs per batch
    int y0 = (blockIdx.x & 255) << 1;

    if (tid == 0) invert3x3(Hp + b * 9, shp);
    if (tid == 1) invert3x3(Ht + b * 9, sht);
    __syncthreads();

    float fx = (float)tid, fy = (float)y0;

    // projective coords at (tid, y0)
    float Xp = fmaf(shp[0], fx, fmaf(shp[1], fy, shp[2]));
    float Yp = fmaf(shp[3], fx, fmaf(shp[4], fy, shp[5]));
    float Zp = fmaf(shp[6], fx, fmaf(shp[7], fy, shp[8]));
    float Xt = fmaf(sht[0], fx, fmaf(sht[1], fy, sht[2]));
    float Yt = fmaf(sht[3], fx, fmaf(sht[4], fy, sht[5]));
    float Zt = fmaf(sht[6], fx, fmaf(sht[7], fy, sht[8]));

    const uint2* img = reinterpret_cast<const uint2*>(g_img) + (size_t)b * PLANE;

    float acc = 0.0f;
#pragma unroll
    for (int r = 0; r < 2; r++) {
        // row base (x = tid, y = y0 + r)
        float rXp = (r == 0) ? Xp : Xp + shp[1];
        float rYp = (r == 0) ? Yp : Yp + shp[4];
        float rZp = (r == 0) ? Zp : Zp + shp[7];
        float rXt = (r == 0) ? Xt : Xt + sht[1];
        float rYt = (r == 0) ? Yt : Yt + sht[4];
        float rZt = (r == 0) ? Zt : Zt + sht[7];

        acc += pixel_mse(img, rXp, rYp, rZp, rXt, rYt, rZt);
        acc += pixel_mse(img,
                         fmaf(shp[0], 256.0f, rXp),
                         fmaf(shp[3], 256.0f, rYp),
                         fmaf(shp[6], 256.0f, rZp),
                         fmaf(sht[0], 256.0f, rXt),
                         fmaf(sht[3], 256.0f, rYt),
                         fmaf(sht[6], 256.0f, rZt));
    }

    // warp shuffle -> smem -> block partial -> self-resetting global reduce
#pragma unroll
    for (int off = 16; off > 0; off >>= 1)
        acc += __shfl_down_sync(0xFFFFFFFFu, acc, off);

    int lane = tid & 31, wid = tid >> 5;
    if (lane == 0) s_part[wid] = acc;
    __syncthreads();
    if (tid == 0) {
        float v = 0.0f;
#pragma unroll
        for (int i = 0; i < THREADS / 32; i++) v += s_part[i];
        atomicAdd(&g_acc, v * INV_NELEM);
        __threadfence();
        unsigned t = atomicInc(&g_ticket, NBLOCKS - 1);   // wraps -> self-reset
        if (t == NBLOCKS - 1) {
            float r = atomicExch(&g_acc, 0.0f);
            out[0] = r;
        }
    }
}

extern "C" void kernel_launch(void* const* d_in, const int* in_sizes, int n_in,
                              void* d_out, int out_size) {
    const float* Hp = (const float*)d_in[0];
    const float* Ht = (const float*)d_in[1];
    const float* I  = (const float*)d_in[2];
    float* out = (float*)d_out;

    interleave_kernel<<<PXTOT / 4 / THREADS, THREADS>>>(I);
    pl_kernel<<<NBLOCKS, THREADS>>>(Hp, Ht, out);
}

// round 7
// speedup vs baseline: 1.1842x; 1.0127x over previous
#include <cuda_runtime.h>
#include <cuda_fp16.h>

#define BATCH     32
#define CHANNELS  3
#define HIMG      512
#define WIMG      512
#define PLANE     (HIMG * WIMG)
#define PXTOT     (BATCH * PLANE)
#define THREADS   256
#define NBLOCKS   (BATCH * HIMG / 2)       // block = (batch, row-pair)
#define INV_NELEM (1.0f / (float)(BATCH * CHANNELS * HIMG * WIMG))

// Padded interleaved image: rows 514 (1 top + 512 + 1 bottom),
// stride 516 px (2 left + 512 + 2 right), 8B per pixel (fp16 c0,c1,c2,pad).
// Borders are never written and __device__ globals zero-init at load ->
// permanently zero -> zero-padding semantics for edge taps.
#define PSTRIDE   516
#define PROWS     514
#define PPLANE    (PROWS * PSTRIDE)
__device__ __half2      g_img[BATCH * PPLANE * 2];   // ~67.9 MB
// self-resetting cross-block reduction state
__device__ float        g_acc;
__device__ unsigned int g_ticket;

// ---------------------------------------------------------------------------
// Prepass: planar fp32 [B,3,H,W] -> padded interleaved fp16x4
// thread = 4 consecutive pixels; dst pixel offset is even -> 16B-aligned
// ---------------------------------------------------------------------------
__global__ void __launch_bounds__(THREADS)
interleave_kernel(const float* __restrict__ I) {
    int t   = blockIdx.x * blockDim.x + threadIdx.x;   // < PXTOT/4
    int px  = t << 2;
    int b   = px >> 18;
    int off = px & (PLANE - 1);
    int y   = off >> 9;
    int x   = off & (WIMG - 1);
    const float* base = I + (size_t)b * (CHANNELS * PLANE) + off;
    float4 c0 = *(const float4*)(base);
    float4 c1 = *(const float4*)(base + PLANE);
    float4 c2 = *(const float4*)(base + 2 * PLANE);

    __half2 o[8];
    o[0] = __floats2half2_rn(c0.x, c1.x);
    o[1] = __floats2half2_rn(c2.x, 0.0f);
    o[2] = __floats2half2_rn(c0.y, c1.y);
    o[3] = __floats2half2_rn(c2.y, 0.0f);
    o[4] = __floats2half2_rn(c0.z, c1.z);
    o[5] = __floats2half2_rn(c2.z, 0.0f);
    o[6] = __floats2half2_rn(c0.w, c1.w);
    o[7] = __floats2half2_rn(c2.w, 0.0f);

    size_t dpx = (size_t)b * PPLANE + (y + 1) * PSTRIDE + (x + 2);
    uint4* dst = reinterpret_cast<uint4*>(g_img + dpx * 2);
    dst[0] = *reinterpret_cast<uint4*>(&o[0]);
    dst[1] = *reinterpret_cast<uint4*>(&o[4]);
}

// ---------------------------------------------------------------------------
// 3x3 inverse via adjugate; X,Y rows prescaled by W/(W-1) so
// sx = X/Z - 0.5 directly.
// ---------------------------------------------------------------------------
#define CSCALE (512.0f / 511.0f)

__device__ __forceinline__ void invert3x3s(const float* __restrict__ m,
                                           float* __restrict__ inv) {
    float c00 = m[4] * m[8] - m[5] * m[7];
    float c01 = m[5] * m[6] - m[3] * m[8];
    float c02 = m[3] * m[7] - m[4] * m[6];
    float det = m[0] * c00 + m[1] * c01 + m[2] * c02;
    float id  = CSCALE / det;        // fold coordinate scale into X,Y rows
    float idz = 1.0f / det;
    inv[0] = c00 * id;
    inv[1] = (m[2] * m[7] - m[1] * m[8]) * id;
    inv[2] = (m[1] * m[5] - m[2] * m[4]) * id;
    inv[3] = c01 * id;
    inv[4] = (m[0] * m[8] - m[2] * m[6]) * id;
    inv[5] = (m[2] * m[3] - m[0] * m[5]) * id;
    inv[6] = c02 * idz;
    inv[7] = (m[1] * m[6] - m[0] * m[7]) * idz;
    inv[8] = (m[0] * m[4] - m[1] * m[3]) * idz;
}

__device__ __forceinline__ float frcp(float x) {
    float r;
    asm("rcp.approx.f32 %0, %1;" : "=f"(r) : "f"(x));
    return r;
}

// ---------------------------------------------------------------------------
// One bilinear sample from the padded image: single validity predicate for
// all 4 taps, unmasked weights (borders are zero), packed HFMA2 accumulation.
// ---------------------------------------------------------------------------
__device__ __forceinline__ void sample3h(const uint2* __restrict__ img,
                                         float X, float Y, float Z,
                                         __half2& a01, __half2& a2) {
    float iz = frcp(Z);
    float sx = fmaf(X, iz, -0.5f);
    float sy = fmaf(Y, iz, -0.5f);
    // clamp: maps NaN/inf to finite invalid coords, leaves valid range intact
    sx = fminf(fmaxf(sx, -2.0f), 513.0f);
    sy = fminf(fmaxf(sy, -2.0f), 513.0f);
    float x0f = floorf(sx), y0f = floorf(sy);
    int x0 = (int)x0f, y0 = (int)y0f;
    bool valid = ((unsigned)(x0 + 1) < 513u) & ((unsigned)(y0 + 1) < 513u);
    float wx1 = sx - x0f, wx0 = 1.0f - wx1;
    float wy1 = sy - y0f, wy0 = 1.0f - wy1;
    int o = (y0 + 1) * PSTRIDE + (x0 + 2);

    __half2 w00 = __float2half2_rn(wx0 * wy0);
    __half2 w10 = __float2half2_rn(wx1 * wy0);
    __half2 w01 = __float2half2_rn(wx0 * wy1);
    __half2 w11 = __float2half2_rn(wx1 * wy1);

    uint2 z = make_uint2(0u, 0u);
    uint2 v00 = valid ? __ldg(img + o)               : z;
    uint2 v10 = valid ? __ldg(img + o + 1)           : z;
    uint2 v01 = valid ? __ldg(img + o + PSTRIDE)     : z;
    uint2 v11 = valid ? __ldg(img + o + PSTRIDE + 1) : z;

    a01 = __hmul2(*reinterpret_cast<__half2*>(&v00.x), w00);
    a2  = __hmul2(*reinterpret_cast<__half2*>(&v00.y), w00);
    a01 = __hfma2(*reinterpret_cast<__half2*>(&v10.x), w10, a01);
    a2  = __hfma2(*reinterpret_cast<__half2*>(&v10.y), w10, a2);
    a01 = __hfma2(*reinterpret_cast<__half2*>(&v01.x), w01, a01);
    a2  = __hfma2(*reinterpret_cast<__half2*>(&v01.y), w01, a2);
    a01 = __hfma2(*reinterpret_cast<__half2*>(&v11.x), w11, a01);
    a2  = __hfma2(*reinterpret_cast<__half2*>(&v11.y), w11, a2);
}

__device__ __forceinline__ float pixel_mse(const uint2* __restrict__ img,
                                           float Xp, float Yp, float Zp,
                                           float Xt, float Yt, float Zt) {
    __half2 p01, p2, t01, t2;
    sample3h(img, Xp, Yp, Zp, p01, p2);
    sample3h(img, Xt, Yt, Zt, t01, t2);
    __half2 d01 = __hsub2(p01, t01);
    __half2 d2  = __hsub2(p2, t2);
    float2 f = __half22float2(d01);
    float  g = __low2float(d2);
    return fmaf(f.x, f.x, fmaf(f.y, f.y, g * g));
}

// ---------------------------------------------------------------------------
// Main kernel: block = (batch, row-pair); thread t handles
// (x=t, y0), (x=t+256, y0), (x=t, y0+1), (x=t+256, y0+1)
// ---------------------------------------------------------------------------
__global__ void __launch_bounds__(THREADS)
pl_kernel(const float* __restrict__ Hp, const float* __restrict__ Ht,
          float* __restrict__ out) {
    __shared__ float shp[9];
    __shared__ float sht[9];
    __shared__ float s_part[THREADS / 32];

    int tid = threadIdx.x;
    int b  = blockIdx.x >> 8;
    int y0 = (blockIdx.x & 255) << 1;

    if (tid == 0) invert3x3s(Hp + b * 9, shp);
    if (tid == 1) invert3x3s(Ht + b * 9, sht);
    __syncthreads();

    float fx = (float)tid, fy = (float)y0;

    float Xp = fmaf(shp[0], fx, fmaf(shp[1], fy, shp[2]));
    float Yp = fmaf(shp[3], fx, fmaf(shp[4], fy, shp[5]));
    float Zp = fmaf(shp[6], fx, fmaf(shp[7], fy, shp[8]));
    float Xt = fmaf(sht[0], fx, fmaf(sht[1], fy, sht[2]));
    float Yt = fmaf(sht[3], fx, fmaf(sht[4], fy, sht[5]));
    float Zt = fmaf(sht[6], fx, fmaf(sht[7], fy, sht[8]));

    const uint2* img = reinterpret_cast<const uint2*>(g_img) + (size_t)b * PPLANE;

    float acc = 0.0f;
#pragma unroll
    for (int r = 0; r < 2; r++) {
        float rXp = (r == 0) ? Xp : Xp + shp[1];
        float rYp = (r == 0) ? Yp : Yp + shp[4];
        float rZp = (r == 0) ? Zp : Zp + shp[7];
        float rXt = (r == 0) ? Xt : Xt + sht[1];
        float rYt = (r == 0) ? Yt : Yt + sht[4];
        float rZt = (r == 0) ? Zt : Zt + sht[7];

        acc += pixel_mse(img, rXp, rYp, rZp, rXt, rYt, rZt);
        acc += pixel_mse(img,
                         fmaf(shp[0], 256.0f, rXp),
                         fmaf(shp[3], 256.0f, rYp),
                         fmaf(shp[6], 256.0f, rZp),
                         fmaf(sht[0], 256.0f, rXt),
                         fmaf(sht[3], 256.0f, rYt),
                         fmaf(sht[6], 256.0f, rZt));
    }

    // warp shuffle -> smem -> block partial -> self-resetting global reduce
#pragma unroll
    for (int off = 16; off > 0; off >>= 1)
        acc += __shfl_down_sync(0xFFFFFFFFu, acc, off);

    int lane = tid & 31, wid = tid >> 5;
    if (lane == 0) s_part[wid] = acc;
    __syncthreads();
    if (tid == 0) {
        float v = 0.0f;
#pragma unroll
        for (int i = 0; i < THREADS / 32; i++) v += s_part[i];
        atomicAdd(&g_acc, v * INV_NELEM);
        __threadfence();
        unsigned t = atomicInc(&g_ticket, NBLOCKS - 1);   // wraps -> self-reset
        if (t == NBLOCKS - 1) {
            float r = atomicExch(&g_acc, 0.0f);
            out[0] = r;
        }
    }
}

extern "C" void kernel_launch(void* const* d_in, const int* in_sizes, int n_in,
                              void* d_out, int out_size) {
    const float* Hp = (const float*)d_in[0];
    const float* Ht = (const float*)d_in[1];
    const float* I  = (const float*)d_in[2];
    float* out = (float*)d_out;

    interleave_kernel<<<PXTOT / 4 / THREADS, THREADS>>>(I);
    pl_kernel<<<NBLOCKS, THREADS>>>(Hp, Ht, out);
}

// round 8
// speedup vs baseline: 1.2031x; 1.0160x over previous
#include <cuda_runtime.h>
#include <cuda_fp16.h>

#define BATCH     32
#define CHANNELS  3
#define HIMG      512
#define WIMG      512
#define PLANE     (HIMG * WIMG)
#define PXTOT     (BATCH * PLANE)
#define THREADS   256
#define NBLOCKS   (BATCH * HIMG / 2)       // block = (batch, row-pair)
#define INV_NELEM (1.0f / (float)(BATCH * CHANNELS * HIMG * WIMG))

// Padded interleaved image: 1-px zero frame (never written; __device__
// globals zero-init at module load -> permanent zero-padding for edge taps).
#define PSTRIDE   516
#define PROWS     514
#define PPLANE    (PROWS * PSTRIDE)
__device__ __half2      g_img[BATCH * PPLANE * 2];   // ~67.9 MB
__device__ float        g_acc;
__device__ unsigned int g_ticket;

// ---------------------------------------------------------------------------
// Prepass: planar fp32 [B,3,H,W] -> padded interleaved fp16x4
// ---------------------------------------------------------------------------
__global__ void __launch_bounds__(THREADS)
interleave_kernel(const float* __restrict__ I) {
    int t   = blockIdx.x * blockDim.x + threadIdx.x;   // < PXTOT/4
    int px  = t << 2;
    int b   = px >> 18;
    int off = px & (PLANE - 1);
    int y   = off >> 9;
    int x   = off & (WIMG - 1);
    const float* base = I + (size_t)b * (CHANNELS * PLANE) + off;
    float4 c0 = *(const float4*)(base);
    float4 c1 = *(const float4*)(base + PLANE);
    float4 c2 = *(const float4*)(base + 2 * PLANE);

    __half2 o[8];
    o[0] = __floats2half2_rn(c0.x, c1.x);
    o[1] = __floats2half2_rn(c2.x, 0.0f);
    o[2] = __floats2half2_rn(c0.y, c1.y);
    o[3] = __floats2half2_rn(c2.y, 0.0f);
    o[4] = __floats2half2_rn(c0.z, c1.z);
    o[5] = __floats2half2_rn(c2.z, 0.0f);
    o[6] = __floats2half2_rn(c0.w, c1.w);
    o[7] = __floats2half2_rn(c2.w, 0.0f);

    size_t dpx = (size_t)b * PPLANE + (y + 1) * PSTRIDE + (x + 2);
    uint4* dst = reinterpret_cast<uint4*>(g_img + dpx * 2);
    dst[0] = *reinterpret_cast<uint4*>(&o[0]);
    dst[1] = *reinterpret_cast<uint4*>(&o[4]);
}

// ---------------------------------------------------------------------------
// 3x3 inverse via adjugate; X,Y rows prescaled by W/(W-1)
// ---------------------------------------------------------------------------
#define CSCALE (512.0f / 511.0f)

__device__ __forceinline__ void invert3x3s(const float* __restrict__ m,
                                           float* __restrict__ inv) {
    float c00 = m[4] * m[8] - m[5] * m[7];
    float c01 = m[5] * m[6] - m[3] * m[8];
    float c02 = m[3] * m[7] - m[4] * m[6];
    float det = m[0] * c00 + m[1] * c01 + m[2] * c02;
    float id  = CSCALE / det;
    float idz = 1.0f / det;
    inv[0] = c00 * id;
    inv[1] = (m[2] * m[7] - m[1] * m[8]) * id;
    inv[2] = (m[1] * m[5] - m[2] * m[4]) * id;
    inv[3] = c01 * id;
    inv[4] = (m[0] * m[8] - m[2] * m[6]) * id;
    inv[5] = (m[2] * m[3] - m[0] * m[5]) * id;
    inv[6] = c02 * idz;
    inv[7] = (m[1] * m[6] - m[0] * m[7]) * idz;
    inv[8] = (m[0] * m[4] - m[1] * m[3]) * idz;
}

__device__ __forceinline__ float frcp(float x) {
    float r;
    asm("rcp.approx.f32 %0, %1;" : "=f"(r) : "f"(x));
    return r;
}

// ---------------------------------------------------------------------------
// One bilinear sample: single validity predicate for all 4 taps, half2
// weight pipeline (packed cvt + HMUL2 + broadcast-selector HFMA2).
// ---------------------------------------------------------------------------
__device__ __forceinline__ void sample3h(const uint2* __restrict__ img,
                                         float X, float Y, float Z,
                                         __half2& a01, __half2& a2) {
    float iz = frcp(Z);
    float sx = fmaf(X, iz, -0.5f);
    float sy = fmaf(Y, iz, -0.5f);
    // clamp: maps NaN/inf to finite invalid coords
    sx = fminf(fmaxf(sx, -2.0f), 513.0f);
    sy = fminf(fmaxf(sy, -2.0f), 513.0f);
    float x0f = floorf(sx), y0f = floorf(sy);
    int x0 = (int)x0f, y0 = (int)y0f;
    bool valid = ((unsigned)(x0 + 1) < 513u) & ((unsigned)(y0 + 1) < 513u);
    float wx1 = sx - x0f, wx0 = 1.0f - wx1;
    float wy1 = sy - y0f, wy0 = 1.0f - wy1;
    int o = (y0 + 1) * PSTRIDE + (x0 + 2);

    // half2 weight pipeline: (wx0,wx1) packed once, two row scalars
    __half2 hwx  = __floats2half2_rn(wx0, wx1);
    __half2 hwy0 = __float2half2_rn(wy0);
    __half2 hwy1 = __float2half2_rn(wy1);
    __half2 wr0  = __hmul2(hwx, hwy0);    // (w00, w10)
    __half2 wr1  = __hmul2(hwx, hwy1);    // (w01, w11)
    __half2 w00 = __half2half2(__low2half(wr0));
    __half2 w10 = __half2half2(__high2half(wr0));
    __half2 w01 = __half2half2(__low2half(wr1));
    __half2 w11 = __half2half2(__high2half(wr1));

    uint2 z = make_uint2(0u, 0u);
    uint2 v00 = valid ? __ldg(img + o)               : z;
    uint2 v10 = valid ? __ldg(img + o + 1)           : z;
    uint2 v01 = valid ? __ldg(img + o + PSTRIDE)     : z;
    uint2 v11 = valid ? __ldg(img + o + PSTRIDE + 1) : z;

    a01 = __hmul2(*reinterpret_cast<__half2*>(&v00.x), w00);
    a2  = __hmul2(*reinterpret_cast<__half2*>(&v00.y), w00);
    a01 = __hfma2(*reinterpret_cast<__half2*>(&v10.x), w10, a01);
    a2  = __hfma2(*reinterpret_cast<__half2*>(&v10.y), w10, a2);
    a01 = __hfma2(*reinterpret_cast<__half2*>(&v01.x), w01, a01);
    a2  = __hfma2(*reinterpret_cast<__half2*>(&v01.y), w01, a2);
    a01 = __hfma2(*reinterpret_cast<__half2*>(&v11.x), w11, a01);
    a2  = __hfma2(*reinterpret_cast<__half2*>(&v11.y), w11, a2);
}

__device__ __forceinline__ float pixel_mse(const uint2* __restrict__ img,
                                           float Xp, float Yp, float Zp,
                                           float Xt, float Yt, float Zt) {
    __half2 p01, p2, t01, t2;
    sample3h(img, Xp, Yp, Zp, p01, p2);
    sample3h(img, Xt, Yt, Zt, t01, t2);
    __half2 d01 = __hsub2(p01, t01);
    __half2 d2  = __hsub2(p2, t2);
    float2 f = __half22float2(d01);
    float  g = __low2float(d2);
    return fmaf(f.x, f.x, fmaf(f.y, f.y, g * g));
}

// ---------------------------------------------------------------------------
// Main kernel: block = (batch, row-pair); thread t handles
// (x=t, y0), (x=t+256, y0), (x=t, y0+1), (x=t+256, y0+1)
// ---------------------------------------------------------------------------
__global__ void __launch_bounds__(THREADS, 7)
pl_kernel(const float* __restrict__ Hp, const float* __restrict__ Ht,
          float* __restrict__ out) {
    __shared__ float shp[9];
    __shared__ float sht[9];
    __shared__ float s_part[THREADS / 32];

    int tid = threadIdx.x;
    int b  = blockIdx.x >> 8;
    int y0 = (blockIdx.x & 255) << 1;

    if (tid == 0) invert3x3s(Hp + b * 9, shp);
    if (tid == 1) invert3x3s(Ht + b * 9, sht);
    __syncthreads();

    float fx = (float)tid, fy = (float)y0;

    float Xp = fmaf(shp[0], fx, fmaf(shp[1], fy, shp[2]));
    float Yp = fmaf(shp[3], fx, fmaf(shp[4], fy, shp[5]));
    float Zp = fmaf(shp[6], fx, fmaf(shp[7], fy, shp[8]));
    float Xt = fmaf(sht[0], fx, fmaf(sht[1], fy, sht[2]));
    float Yt = fmaf(sht[3], fx, fmaf(sht[4], fy, sht[5]));
    float Zt = fmaf(sht[6], fx, fmaf(sht[7], fy, sht[8]));

    const uint2* img = reinterpret_cast<const uint2*>(g_img) + (size_t)b * PPLANE;

    float acc = 0.0f;
#pragma unroll
    for (int r = 0; r < 2; r++) {
        float rXp = (r == 0) ? Xp : Xp + shp[1];
        float rYp = (r == 0) ? Yp : Yp + shp[4];
        float rZp = (r == 0) ? Zp : Zp + shp[7];
        float rXt = (r == 0) ? Xt : Xt + sht[1];
        float rYt = (r == 0) ? Yt : Yt + sht[4];
        float rZt = (r == 0) ? Zt : Zt + sht[7];

        acc += pixel_mse(img, rXp, rYp, rZp, rXt, rYt, rZt);
        acc += pixel_mse(img,
                         fmaf(shp[0], 256.0f, rXp),
                         fmaf(shp[3], 256.0f, rYp),
                         fmaf(shp[6], 256.0f, rZp),
                         fmaf(sht[0], 256.0f, rXt),
                         fmaf(sht[3], 256.0f, rYt),
                         fmaf(sht[6], 256.0f, rZt));
    }

#pragma unroll
    for (int off = 16; off > 0; off >>= 1)
        acc += __shfl_down_sync(0xFFFFFFFFu, acc, off);

    int lane = tid & 31, wid = tid >> 5;
    if (lane == 0) s_part[wid] = acc;
    __syncthreads();
    if (tid == 0) {
        float v = 0.0f;
#pragma unroll
        for (int i = 0; i < THREADS / 32; i++) v += s_part[i];
        atomicAdd(&g_acc, v * INV_NELEM);
        __threadfence();
        unsigned t = atomicInc(&g_ticket, NBLOCKS - 1);   // wraps -> self-reset
        if (t == NBLOCKS - 1) {
            float r = atomicExch(&g_acc, 0.0f);
            out[0] = r;
        }
    }
}

extern "C" void kernel_launch(void* const* d_in, const int* in_sizes, int n_in,
                              void* d_out, int out_size) {
    const float* Hp = (const float*)d_in[0];
    const float* Ht = (const float*)d_in[1];
    const float* I  = (const float*)d_in[2];
    float* out = (float*)d_out;

    interleave_kernel<<<PXTOT / 4 / THREADS, THREADS>>>(I);
    pl_kernel<<<NBLOCKS, THREADS>>>(Hp, Ht, out);
}

// round 9
// speedup vs baseline: 1.2479x; 1.0373x over previous
#include <cuda_runtime.h>
#include <cuda_fp16.h>

#define BATCH     32
#define CHANNELS  3
#define HIMG      512
#define WIMG      512
#define PLANE     (HIMG * WIMG)
#define PXTOT     (BATCH * PLANE)
#define THREADS   256
#define ROWS_PER_BLOCK 4
#define NBLOCKS   (BATCH * HIMG / ROWS_PER_BLOCK)   // 4096
#define INV_NELEM (1.0f / (float)(BATCH * CHANNELS * HIMG * WIMG))

// Padded interleaved image: 1-px zero frame (never written; __device__
// globals zero-init at module load -> permanent zero-padding for edge taps).
#define PSTRIDE   516
#define PROWS     514
#define PPLANE    (PROWS * PSTRIDE)
__device__ __half2      g_img[BATCH * PPLANE * 2];   // ~67.9 MB
__device__ float        g_acc;
__device__ unsigned int g_ticket;

// ---------------------------------------------------------------------------
// Prepass: planar fp32 [B,3,H,W] -> padded interleaved fp16x4
// ---------------------------------------------------------------------------
__global__ void __launch_bounds__(THREADS)
interleave_kernel(const float* __restrict__ I) {
    int t   = blockIdx.x * blockDim.x + threadIdx.x;   // < PXTOT/4
    int px  = t << 2;
    int b   = px >> 18;
    int off = px & (PLANE - 1);
    int y   = off >> 9;
    int x   = off & (WIMG - 1);
    const float* base = I + (size_t)b * (CHANNELS * PLANE) + off;
    float4 c0 = *(const float4*)(base);
    float4 c1 = *(const float4*)(base + PLANE);
    float4 c2 = *(const float4*)(base + 2 * PLANE);

    __half2 o[8];
    o[0] = __floats2half2_rn(c0.x, c1.x);
    o[1] = __floats2half2_rn(c2.x, 0.0f);
    o[2] = __floats2half2_rn(c0.y, c1.y);
    o[3] = __floats2half2_rn(c2.y, 0.0f);
    o[4] = __floats2half2_rn(c0.z, c1.z);
    o[5] = __floats2half2_rn(c2.z, 0.0f);
    o[6] = __floats2half2_rn(c0.w, c1.w);
    o[7] = __floats2half2_rn(c2.w, 0.0f);

    size_t dpx = (size_t)b * PPLANE + (y + 1) * PSTRIDE + (x + 2);
    uint4* dst = reinterpret_cast<uint4*>(g_img + dpx * 2);
    dst[0] = *reinterpret_cast<uint4*>(&o[0]);
    dst[1] = *reinterpret_cast<uint4*>(&o[4]);
}

// ---------------------------------------------------------------------------
// 3x3 inverse via adjugate; X,Y rows prescaled by W/(W-1)
// ---------------------------------------------------------------------------
#define CSCALE (512.0f / 511.0f)

__device__ __forceinline__ void invert3x3s(const float* __restrict__ m,
                                           float* __restrict__ inv) {
    float c00 = m[4] * m[8] - m[5] * m[7];
    float c01 = m[5] * m[6] - m[3] * m[8];
    float c02 = m[3] * m[7] - m[4] * m[6];
    float det = m[0] * c00 + m[1] * c01 + m[2] * c02;
    float id  = CSCALE / det;
    float idz = 1.0f / det;
    inv[0] = c00 * id;
    inv[1] = (m[2] * m[7] - m[1] * m[8]) * id;
    inv[2] = (m[1] * m[5] - m[2] * m[4]) * id;
    inv[3] = c01 * id;
    inv[4] = (m[0] * m[8] - m[2] * m[6]) * id;
    inv[5] = (m[2] * m[3] - m[0] * m[5]) * id;
    inv[6] = c02 * idz;
    inv[7] = (m[1] * m[6] - m[0] * m[7]) * idz;
    inv[8] = (m[0] * m[4] - m[1] * m[3]) * idz;
}

__device__ __forceinline__ float frcp(float x) {
    float r;
    asm("rcp.approx.f32 %0, %1;" : "=f"(r) : "f"(x));
    return r;
}

// ---------------------------------------------------------------------------
// One bilinear sample: unconditional LDG.64 x4; invalid samples are
// redirected to offset whose 4 taps all hit the permanently-zero border.
// Coord clamps keep weights finite for inf coords (0-weight x 0-data safe).
// ---------------------------------------------------------------------------
__device__ __forceinline__ void sample3h(const uint2* __restrict__ img,
                                         float X, float Y, float Z,
                                         __half2& a01, __half2& a2) {
    float iz = frcp(Z);
    float sx = fmaf(X, iz, -0.5f);
    float sy = fmaf(Y, iz, -0.5f);
    sx = fminf(fmaxf(sx, -2.0f), 513.0f);
    sy = fminf(fmaxf(sy, -2.0f), 513.0f);
    float x0f = floorf(sx), y0f = floorf(sy);
    int x0 = (int)x0f, y0 = (int)y0f;
    bool valid = ((unsigned)(x0 + 1) < 513u) & ((unsigned)(y0 + 1) < 513u);
    float wx1 = sx - x0f, wx0 = 1.0f - wx1;
    float wy1 = sy - y0f, wy0 = 1.0f - wy1;
    // o + PAD_OFF = linear pixel index; redirect invalid to 0 (border corner:
    // taps 0,1,PSTRIDE,PSTRIDE+1 are all in the zero frame)
    int o = y0 * PSTRIDE + x0;
    o = valid ? o : -(PSTRIDE + 2);

    __half2 hwx  = __floats2half2_rn(wx0, wx1);
    __half2 hwy0 = __float2half2_rn(wy0);
    __half2 hwy1 = __float2half2_rn(wy1);
    __half2 wr0  = __hmul2(hwx, hwy0);    // (w00, w10)
    __half2 wr1  = __hmul2(hwx, hwy1);    // (w01, w11)
    __half2 w00 = __half2half2(__low2half(wr0));
    __half2 w10 = __half2half2(__high2half(wr0));
    __half2 w01 = __half2half2(__low2half(wr1));
    __half2 w11 = __half2half2(__high2half(wr1));

    const uint2* p = img + o + (PSTRIDE + 2);
    uint2 v00 = __ldg(p);
    uint2 v10 = __ldg(p + 1);
    uint2 v01 = __ldg(p + PSTRIDE);
    uint2 v11 = __ldg(p + PSTRIDE + 1);

    a01 = __hmul2(*reinterpret_cast<__half2*>(&v00.x), w00);
    a2  = __hmul2(*reinterpret_cast<__half2*>(&v00.y), w00);
    a01 = __hfma2(*reinterpret_cast<__half2*>(&v10.x), w10, a01);
    a2  = __hfma2(*reinterpret_cast<__half2*>(&v10.y), w10, a2);
    a01 = __hfma2(*reinterpret_cast<__half2*>(&v01.x), w01, a01);
    a2  = __hfma2(*reinterpret_cast<__half2*>(&v01.y), w01, a2);
    a01 = __hfma2(*reinterpret_cast<__half2*>(&v11.x), w11, a01);
    a2  = __hfma2(*reinterpret_cast<__half2*>(&v11.y), w11, a2);
}

__device__ __forceinline__ float pixel_mse(const uint2* __restrict__ img,
                                           float Xp, float Yp, float Zp,
                                           float Xt, float Yt, float Zt) {
    __half2 p01, p2, t01, t2;
    sample3h(img, Xp, Yp, Zp, p01, p2);
    sample3h(img, Xt, Yt, Zt, t01, t2);
    __half2 d01 = __hsub2(p01, t01);
    __half2 d2  = __hsub2(p2, t2);
    float2 f = __half22float2(d01);
    float  g = __low2float(d2);
    return fmaf(f.x, f.x, fmaf(f.y, f.y, g * g));
}

// ---------------------------------------------------------------------------
// Main kernel: block = (batch, 4-row band); thread t handles
// x = t and x = t+256 for each of the 4 rows (8 pixels)
// ---------------------------------------------------------------------------
__global__ void __launch_bounds__(THREADS, 7)
pl_kernel(const float* __restrict__ Hp, const float* __restrict__ Ht,
          float* __restrict__ out) {
    __shared__ float shp[9];
    __shared__ float sht[9];
    __shared__ float s_part[THREADS / 32];

    int tid = threadIdx.x;
    int b  = blockIdx.x >> 7;                 // 128 bands per batch
    int y0 = (blockIdx.x & 127) << 2;

    if (tid == 0) invert3x3s(Hp + b * 9, shp);
    if (tid == 1) invert3x3s(Ht + b * 9, sht);
    __syncthreads();

    float fx = (float)tid, fy = (float)y0;

    // running projective coords at (tid, y) and per-row increments
    float Xp = fmaf(shp[0], fx, fmaf(shp[1], fy, shp[2]));
    float Yp = fmaf(shp[3], fx, fmaf(shp[4], fy, shp[5]));
    float Zp = fmaf(shp[6], fx, fmaf(shp[7], fy, shp[8]));
    float Xt = fmaf(sht[0], fx, fmaf(sht[1], fy, sht[2]));
    float Yt = fmaf(sht[3], fx, fmaf(sht[4], fy, sht[5]));
    float Zt = fmaf(sht[6], fx, fmaf(sht[7], fy, sht[8]));

    // stride-256 column offsets (constant per thread)
    float dXp = shp[0] * 256.0f, dYp = shp[3] * 256.0f, dZp = shp[6] * 256.0f;
    float dXt = sht[0] * 256.0f, dYt = sht[3] * 256.0f, dZt = sht[6] * 256.0f;

    const uint2* img = reinterpret_cast<const uint2*>(g_img) + (size_t)b * PPLANE;

    float acc = 0.0f;
#pragma unroll
    for (int r = 0; r < ROWS_PER_BLOCK; r++) {
        acc += pixel_mse(img, Xp, Yp, Zp, Xt, Yt, Zt);
        acc += pixel_mse(img, Xp + dXp, Yp + dYp, Zp + dZp,
                              Xt + dXt, Yt + dYt, Zt + dZt);
        if (r < ROWS_PER_BLOCK - 1) {
            Xp += shp[1]; Yp += shp[4]; Zp += shp[7];
            Xt += sht[1]; Yt += sht[4]; Zt += sht[7];
        }
    }

#pragma unroll
    for (int off = 16; off > 0; off >>= 1)
        acc += __shfl_down_sync(0xFFFFFFFFu, acc, off);

    int lane = tid & 31, wid = tid >> 5;
    if (lane == 0) s_part[wid] = acc;
    __syncthreads();
    if (tid == 0) {
        float v = 0.0f;
#pragma unroll
        for (int i = 0; i < THREADS / 32; i++) v += s_part[i];
        atomicAdd(&g_acc, v * INV_NELEM);
        __threadfence();
        unsigned t = atomicInc(&g_ticket, NBLOCKS - 1);   // wraps -> self-reset
        if (t == NBLOCKS - 1) {
            float r = atomicExch(&g_acc, 0.0f);
            out[0] = r;
        }
    }
}

extern "C" void kernel_launch(void* const* d_in, const int* in_sizes, int n_in,
                              void* d_out, int out_size) {
    const float* Hp = (const float*)d_in[0];
    const float* Ht = (const float*)d_in[1];
    const float* I  = (const float*)d_in[2];
    float* out = (float*)d_out;

    interleave_kernel<<<PXTOT / 4 / THREADS, THREADS>>>(I);
    pl_kernel<<<NBLOCKS, THREADS>>>(Hp, Ht, out);
}